// round 6
// baseline (speedup 1.0000x reference)
#include <cuda_runtime.h>

typedef unsigned long long u64;

#define TW 59
#define TH 32
#define HIN 128
#define WIN 128
#define HOUT 236
#define WOUT 236
#define C1F 0.84852813742385702928f   // 0.6*sqrt(2)
#define C2F 0.56568542494923801952f   // 0.4*sqrt(2)

// Dynamic SMEM layout (floats):
#define T1P   136                      // sT1 pitch (25 rows)
#define INP   39                       // sIN pitch (24 rows)
#define IN_OFF   (25 * T1P)            // 3400
#define A_SIZE   (IN_OFF + 24 * INP)   // 4336 (region A: sT1+sIN; aliased by sM[32][130])
#define ZMP   130                      // zM pitch (76 rows)
#define ZM_OFF   A_SIZE                // region B: zM; aliased by sOut[32][61]
#define KU_OFF   (ZM_OFF + 76 * ZMP)   // 14216
#define KD_OFF   (KU_OFF + 24)
#define SMEM_FLOATS (KD_OFF + 12)      // 14252 -> 57008 bytes

__device__ __forceinline__ u64 pk2(float lo, float hi) {
    u64 r; asm("mov.b64 %0,{%1,%2};" : "=l"(r) : "f"(lo), "f"(hi)); return r;
}
__device__ __forceinline__ u64 fma2(u64 a, u64 b, u64 c) {
    u64 r; asm("fma.rn.f32x2 %0,%1,%2,%3;" : "=l"(r) : "l"(a), "l"(b), "l"(c)); return r;
}
__device__ __forceinline__ u64 mul2(u64 a, u64 b) {
    u64 r; asm("mul.rn.f32x2 %0,%1,%2;" : "=l"(r) : "l"(a), "l"(b)); return r;
}

// Polyphase algebra (global coords, verified R1-R3):
//   z col Zg: phase=(Zg+2)&3, input cols ((Zg+10)>>2)-j, j=0..5 ; same vertically.
//   out col Xg reads z cols [2*Xg+15, 2*Xg+26].
// Tile: outputs [y0,y0+32) x [x0,x0+59); local z col cc = Zg-(2*x0+15), stored in sT1 at cc+4.

__global__ __launch_bounds__(256, 4) void afa_kernel(
    const float* __restrict__ x, const float* __restrict__ bias,
    const float* __restrict__ kup, const float* __restrict__ kdn,
    float* __restrict__ out)
{
    extern __shared__ float smem[];
    float* __restrict__ sT1  = smem;            // [25][136]  H-up result (col+4)
    float* __restrict__ sIN  = smem + IN_OFF;   // [24][39]   input patch
    float* __restrict__ zM   = smem + ZM_OFF;   // [76][130]  z = lrelu(V-up)
    float* __restrict__ sM   = smem;            // [32][130]  V-down result (alias A)
    float* __restrict__ sOut = smem + ZM_OFF;   // [32][61]   final tile (alias B)
    float* __restrict__ sku  = smem + KU_OFF;
    float* __restrict__ skd  = smem + KD_OFF;

    const int tid = threadIdx.x;
    const int bz  = blockIdx.z;
    const int y0  = blockIdx.y * TH;
    const int x0  = blockIdx.x * TW;

    if (tid < 24)       sku[tid]      = kup[tid];
    else if (tid < 36)  skd[tid - 24] = kdn[tid - 24];

    const int Zbase = 2 * x0 + 15;
    const int smin  = (Zbase + 10) >> 2;
    const int IC0   = smin - 5;
    const int IR0   = (y0 >> 1) + 1;
    const int off   = 4 * smin - 10 - Zbase;    // -1 or -3

    const float bv = bias[bz & 255];
    const float* __restrict__ xp = x + (long long)bz * (HIN * WIN);

    // ---- Stage 1: load 24x38 input patch + bias ----
    {
        const int c = tid & 31;
        #pragma unroll
        for (int r = tid >> 5; r < 24; r += 8) {
            const int gr = min(IR0 + r, HIN - 1) * WIN;
            sIN[r * INP + c] = xp[gr + min(IC0 + c, WIN - 1)] + bv;
            if (c < 6)
                sIN[r * INP + c + 32] = xp[gr + min(IC0 + c + 32, WIN - 1)] + bv;
        }
    }
    __syncthreads();

    // ---- Stage 2: horizontal 4x upsample, phase-blocked ----
    {
        float ku[24];
        #pragma unroll
        for (int i = 0; i < 24; i++) ku[i] = sku[i];
        for (int idx = tid; idx < 33 * 24; idx += 256) {
            int n  = idx % 24;             // lanes walk rows; pitch 39 conflict-free
            int si = idx / 24;
            float a0 = 0.f, a1 = 0.f, a2 = 0.f, a3 = 0.f;
            #pragma unroll
            for (int j = 0; j < 6; j++) {
                float v = sIN[n * INP + si + 5 - j];
                a0 += ku[4 * j + 0] * v;
                a1 += ku[4 * j + 1] * v;
                a2 += ku[4 * j + 2] * v;
                a3 += ku[4 * j + 3] * v;
            }
            int cb = 4 * si + off + 4;     // odd in [1,131]
            sT1[n * T1P + cb] = a0;
            *(float2*)&sT1[n * T1P + cb + 1] = make_float2(a1, a2);  // even -> STS.64
            sT1[n * T1P + cb + 3] = a3;
        }
    }
    __syncthreads();

    // ---- Stage 3a: vertical 4x upsample + lrelu*sqrt2, packed f32x2 ----
    // thread = (phase p, column pair cp); z rows of phase p: ii = first + 4k.
    {
        const int p     = tid >> 6;
        const int cp    = tid & 63;
        const int first = (p - 1) & 3;                 // 0,1,2,3 for p=1,2,3,0
        const int m0    = ((first + 25) >> 2) - 1;     // 5 (p!=0) or 6 (p=0)
        const int cc4   = 2 * cp + 4;

        u64 ku2[6];
        #pragma unroll
        for (int j = 0; j < 6; j++) { float v = sku[4 * j + p]; ku2[j] = pk2(v, v); }
        const u64 C1P = pk2(C1F, C1F), C2P = pk2(C2F, C2F);

        u64 w[6];
        #pragma unroll
        for (int j = 0; j < 6; j++) w[j] = *(const u64*)&sT1[(m0 - 5 + j) * T1P + cc4];

        int zr = first;
        #pragma unroll
        for (int k = 0; k < 19; k++) {                 // rows >73 write scratch rows 74/75 (never read)
            if (k > 0) {
                #pragma unroll
                for (int j = 0; j < 5; j++) w[j] = w[j + 1];
                w[5] = *(const u64*)&sT1[(m0 + k) * T1P + cc4];
            }
            u64 a = mul2(w[5], ku2[0]);
            #pragma unroll
            for (int j = 1; j < 6; j++) a = fma2(w[5 - j], ku2[j], a);
            u64 t = mul2(a, C1P);
            u64 r = fma2(a & 0x7FFFFFFF7FFFFFFFULL, C2P, t);   // lrelu*sqrt2, packed
            *(u64*)&zM[zr * ZMP + 2 * cp] = r;
            zr += 4;
        }
    }
    __syncthreads();

    // ---- Stage 3b: vertical 2x downsample, packed f32x2, rolling 12-row window ----
    {
        const int g    = tid >> 6;
        const int cp   = tid & 63;
        const int base = 16 * g;                       // outputs yl = 8g..8g+7

        u64 kd2[6];                                    // 12-tap filter is even-symmetric
        #pragma unroll
        for (int u = 0; u < 6; u++) { float v = skd[u]; kd2[u] = pk2(v, v); }

        u64 zw[12];
        #pragma unroll
        for (int rr = 0; rr < 10; rr++) zw[rr] = *(const u64*)&zM[(base + rr) * ZMP + 2 * cp];

        #pragma unroll
        for (int l = 0; l < 8; l++) {
            zw[(2 * l + 10) % 12] = *(const u64*)&zM[(base + 2 * l + 10) * ZMP + 2 * cp];
            zw[(2 * l + 11) % 12] = *(const u64*)&zM[(base + 2 * l + 11) * ZMP + 2 * cp];
            u64 acc = mul2(zw[(2 * l + 11) % 12], kd2[0]);
            #pragma unroll
            for (int t = 1; t < 12; t++) {
                const int u = t < 6 ? t : 11 - t;
                acc = fma2(zw[(2 * l + 11 - t) % 12], kd2[u], acc);
            }
            *(u64*)&sM[(8 * g + l) * ZMP + 2 * cp] = acc;
        }
    }
    __syncthreads();

    // ---- Stage 4: horizontal 2x downsample ----
    {
        float kd[12];
        #pragma unroll
        for (int i = 0; i < 12; i++) kd[i] = skd[i];
        float (*so)[61] = (float (*)[61])sOut;
        for (int idx = tid; idx < 15 * 32; idx += 256) {
            int g = idx >> 5, yl = idx & 31;           // lanes walk yl; even pitch -> LDS.64 OK
            const float2* __restrict__ row2 = (const float2*)&sM[yl * ZMP + 8 * g];
            float r[18];
            #pragma unroll
            for (int k = 0; k < 9; k++) {
                float2 v = row2[k];
                r[2 * k] = v.x; r[2 * k + 1] = v.y;
            }
            #pragma unroll
            for (int q = 0; q < 4; q++) {
                int xl = 4 * g + q;
                if (xl < TW) {
                    float acc = 0.f;
                    #pragma unroll
                    for (int t = 0; t < 12; t++) acc += kd[t] * r[2 * q + 11 - t];
                    so[yl][xl] = acc;
                }
            }
        }
    }
    __syncthreads();

    // ---- Stage 5: coalesced store ----
    {
        float* __restrict__ op = out + (long long)bz * (HOUT * WOUT);
        float (*so)[61] = (float (*)[61])sOut;
        for (int idx = tid; idx < TH * TW; idx += 256) {
            int yl = idx / TW, xl = idx - yl * TW;
            int yg = y0 + yl;
            if (yg < HOUT) op[yg * WOUT + x0 + xl] = so[yl][xl];
        }
    }
}

extern "C" void kernel_launch(void* const* d_in, const int* in_sizes, int n_in,
                              void* d_out, int out_size)
{
    const float* x   = (const float*)d_in[0];
    const float* b   = (const float*)d_in[1];
    const float* kup = (const float*)d_in[2];
    const float* kdn = (const float*)d_in[3];
    float* out = (float*)d_out;

    cudaFuncSetAttribute(afa_kernel, cudaFuncAttributeMaxDynamicSharedMemorySize,
                         SMEM_FLOATS * 4);
    dim3 grid(WOUT / TW, (HOUT + TH - 1) / TH, 4 * 256);   // 4 x 8 x 1024
    afa_kernel<<<grid, 256, SMEM_FLOATS * 4>>>(x, b, kup, kdn, out);
}